// round 17
// baseline (speedup 1.0000x reference)
#include <cuda_runtime.h>
#include <cstdint>

// Problem constants
#define HW2        65536      // 256*256 pixels
#define N_PIX      65536
#define N_Q        16384      // pixel quads (float4 granularity)
#define BATCH      64
#define COV_Q      128        // quads per covar block
#define NBLK_COV   128        // 16384 / 128

// TMA pipeline for covar
#define STAGE_B    2                          // batches per stage
#define N_STAGES   (BATCH / STAGE_B)          // 32
#define NBUF       3                          // pipeline depth
#define CHUNK      (COV_Q * 16)               // 2048 B per (batch,plane) chunk
#define STAGE_BYTES (STAGE_B * 3 * CHUNK)     // 12288 B

// Scratch (allocation-free rule: __device__ globals)
__device__ float g_G[6 * N_PIX];       // covariance planes g00,g01,g02,g11,g12,g22
__device__ float g_mats[18 * N_PIX];   // A(9), 8L(6), d(3) — plane-major
__device__ float g_partial[NBLK_COV];  // per-block trace partial sums

// ---- float4 helpers --------------------------------------------------------
__device__ __forceinline__ float4 f4mul(float4 a, float4 b) {
    return make_float4(a.x * b.x, a.y * b.y, a.z * b.z, a.w * b.w);
}
__device__ __forceinline__ float4 f4fma(float4 a, float4 b, float4 c) {
    return make_float4(fmaf(a.x, b.x, c.x), fmaf(a.y, b.y, c.y),
                       fmaf(a.z, b.z, c.z), fmaf(a.w, b.w, c.w));
}
__device__ __forceinline__ float4 f4neg(float4 a) {
    return make_float4(-a.x, -a.y, -a.z, -a.w);
}
__device__ __forceinline__ float4 f4add(float4 a, float4 b) {
    return make_float4(a.x + b.x, a.y + b.y, a.z + b.z, a.w + b.w);
}
__device__ __forceinline__ float4 f4scale(float4 a, float s) {
    return make_float4(a.x * s, a.y * s, a.z * s, a.w * s);
}

__device__ __forceinline__ uint32_t smem_u32(const void* p) {
    uint32_t a;
    asm("{ .reg .u64 t; cvta.to.shared.u64 t, %1; cvt.u32.u64 %0, t; }"
        : "=r"(a) : "l"(p));
    return a;
}

__device__ __forceinline__ void mbar_init(uint32_t mbar, uint32_t count) {
    asm volatile("mbarrier.init.shared.b64 [%0], %1;" :: "r"(mbar), "r"(count) : "memory");
}
__device__ __forceinline__ void mbar_expect_tx(uint32_t mbar, uint32_t bytes) {
    asm volatile("mbarrier.arrive.expect_tx.shared.b64 _, [%0], %1;"
                 :: "r"(mbar), "r"(bytes) : "memory");
}
__device__ __forceinline__ void bulk_g2s(uint32_t dst_smem, const void* src_gmem,
                                         uint32_t bytes, uint32_t mbar) {
    asm volatile(
        "cp.async.bulk.shared::cta.global.mbarrier::complete_tx::bytes "
        "[%0], [%1], %2, [%3];"
        :: "r"(dst_smem), "l"(src_gmem), "r"(bytes), "r"(mbar) : "memory");
}
__device__ __forceinline__ void mbar_wait_parity(uint32_t mbar, uint32_t parity) {
    uint32_t done;
    asm volatile(
        "{\n\t.reg .pred p;\n\t"
        "mbarrier.try_wait.parity.acquire.cta.shared::cta.b64 p, [%1], %2;\n\t"
        "selp.b32 %0, 1, 0, p;\n\t}"
        : "=r"(done) : "r"(mbar), "r"(parity) : "memory");
    if (!done) {
        asm volatile(
            "{\n\t.reg .pred P1;\n\t"
            "WL_%=:\n\t"
            "mbarrier.try_wait.parity.acquire.cta.shared::cta.b64 P1, [%0], %1, 0x989680;\n\t"
            "@P1 bra.uni WD_%=;\n\t"
            "bra.uni WL_%=;\n\t"
            "WD_%=:\n\t}"
            :: "r"(mbar), "r"(parity) : "memory");
    }
}

// ---------------------------------------------------------------------------
// Kernel 1: per-pixel covariance via TMA bulk pipeline.
// 128 blocks x 128 threads; thread = one quad, accumulates all 64 batches.
// cp.async.bulk streams (batch,plane) 2KB chunks into a 3-deep x 12KB smem
// pipeline — in-flight bytes tracked by mbarrier, NOT registers, breaking the
// register-capped-MLP floor (~4.1 TB/s) of every LDG variant.
// ---------------------------------------------------------------------------
__global__ __launch_bounds__(128, 1) void k_covar(const float4* __restrict__ s4) {
    __shared__ __align__(16) float4 buf[NBUF][STAGE_B * 3][COV_Q];  // 36 KB
    __shared__ __align__(8) uint64_t mbar[NBUF];
    __shared__ float shr[4];

    const int tid = threadIdx.x;                 // quad-local 0..127
    const uint32_t mb0 = smem_u32(&mbar[0]);
    const char* src_base = (const char*)s4 + (size_t)blockIdx.x * CHUNK;

    if (tid == 0) {
#pragma unroll
        for (int k = 0; k < NBUF; ++k) mbar_init(mb0 + 8 * k, 1);
    }
    __syncthreads();

    // prologue: fill all NBUF stages
    if (tid == 0) {
#pragma unroll
        for (int s = 0; s < NBUF; ++s) {
            const uint32_t mb = mb0 + 8 * s;
            mbar_expect_tx(mb, STAGE_BYTES);
#pragma unroll
            for (int c = 0; c < STAGE_B * 3; ++c) {
                // chunk c of stage s: batch = s*STAGE_B + c/3, plane = c%3
                const int b  = s * STAGE_B + c / 3;
                const int pl = c % 3;
                bulk_g2s(smem_u32(&buf[s][c][0]),
                         src_base + ((size_t)b * 3 + pl) * (N_Q * 16),
                         CHUNK, mb);
            }
        }
    }

    float4 a0 = make_float4(0.f, 0.f, 0.f, 0.f);
    float4 a1 = a0, a2 = a0, a3 = a0, a4 = a0, a5 = a0;

    int bufi = 0, phase = 0;
    for (int i = 0; i < N_STAGES; ++i) {
        mbar_wait_parity(mb0 + 8 * bufi, phase);

#pragma unroll
        for (int bi = 0; bi < STAGE_B; ++bi) {
            const float4 s0 = buf[bufi][bi * 3 + 0][tid];
            const float4 s1 = buf[bufi][bi * 3 + 1][tid];
            const float4 s2 = buf[bufi][bi * 3 + 2][tid];
            a0 = f4fma(s0, s0, a0); a1 = f4fma(s0, s1, a1); a2 = f4fma(s0, s2, a2);
            a3 = f4fma(s1, s1, a3); a4 = f4fma(s1, s2, a4); a5 = f4fma(s2, s2, a5);
        }
        __syncthreads();   // all threads done with this buffer

        const int next = i + NBUF;
        if (next < N_STAGES && tid == 0) {
            const uint32_t mb = mb0 + 8 * bufi;
            mbar_expect_tx(mb, STAGE_BYTES);
#pragma unroll
            for (int c = 0; c < STAGE_B * 3; ++c) {
                const int b  = next * STAGE_B + c / 3;
                const int pl = c % 3;
                bulk_g2s(smem_u32(&buf[bufi][c][0]),
                         src_base + ((size_t)b * 3 + pl) * (N_Q * 16),
                         CHUNK, mb);
            }
        }
        if (++bufi == NBUF) { bufi = 0; phase ^= 1; }
    }

    // scale + store covariance planes (coalesced 2KB per plane)
    const float ib = 1.0f / 64.0f;
    a0 = f4scale(a0, ib); a1 = f4scale(a1, ib); a2 = f4scale(a2, ib);
    a3 = f4scale(a3, ib); a4 = f4scale(a4, ib); a5 = f4scale(a5, ib);

    const int q = blockIdx.x * COV_Q + tid;
    float4* g4 = (float4*)g_G;
    g4[0 * N_Q + q] = a0; g4[1 * N_Q + q] = a1; g4[2 * N_Q + q] = a2;
    g4[3 * N_Q + q] = a3; g4[4 * N_Q + q] = a4; g4[5 * N_Q + q] = a5;

    // trace partial for this block
    const float4 td = f4add(f4add(a0, a3), a5);
    float tr = td.x + td.y + td.z + td.w;
#pragma unroll
    for (int o = 16; o > 0; o >>= 1)
        tr += __shfl_down_sync(0xffffffffu, tr, o);
    if ((tid & 31) == 0) shr[tid >> 5] = tr;
    __syncthreads();
    if (tid == 0)
        g_partial[blockIdx.x] = shr[0] + shr[1] + shr[2] + shr[3];
}

// ---------------------------------------------------------------------------
// Kernel 2: per-pixel matrix prep (fp32).  (unchanged from 64.0us baseline)
// ---------------------------------------------------------------------------
__global__ __launch_bounds__(256) void k_prep(const float* __restrict__ t) {
    __shared__ float sh_sum;
    {
        float v = (threadIdx.x < NBLK_COV) ? g_partial[threadIdx.x] : 0.f;
#pragma unroll
        for (int o = 16; o > 0; o >>= 1)
            v += __shfl_down_sync(0xffffffffu, v, o);
        __shared__ float sh[8];
        const int lane = threadIdx.x & 31;
        const int w    = threadIdx.x >> 5;
        if (lane == 0) sh[w] = v;
        __syncthreads();
        if (threadIdx.x == 0) {
            float acc = 0.f;
#pragma unroll
            for (int i = 0; i < 8; ++i) acc += sh[i];
            sh_sum = acc;
        }
        __syncthreads();
    }

    const int p = blockIdx.x * blockDim.x + threadIdx.x;
    const float t0 = __ldg(t);
    const float diag_mean = sh_sum / (65536.0f * 3.0f);
    const float norm  = (t0 == 1.0f) ? diag_mean * 4.0f : 1.0f;
    const float alpha = 0.5f * __expf(-4.5f * (1.0f - t0));
    const float sa = alpha / norm;
    const float diag_add = (1.0f - alpha) * 0.25f;

    const float a00 = g_G[0 * N_PIX + p] * sa + diag_add;
    const float a01 = g_G[1 * N_PIX + p] * sa;
    const float a02 = g_G[2 * N_PIX + p] * sa;
    const float a11 = g_G[3 * N_PIX + p] * sa + diag_add;
    const float a12 = g_G[4 * N_PIX + p] * sa;
    const float a22 = g_G[5 * N_PIX + p] * sa + diag_add;

    // adjugate inverse (fp32)
    const float c00 = a11 * a22 - a12 * a12;
    const float c01 = a02 * a12 - a01 * a22;
    const float c02 = a01 * a12 - a02 * a11;
    const float det = a00 * c00 + a01 * c01 + a02 * c02;
    const float id  = 1.0f / det;
    const float i00 = c00 * id;
    const float i01 = c01 * id;
    const float i02 = c02 * id;
    const float i11 = (a00 * a22 - a02 * a02) * id;
    const float i12 = (a01 * a02 - a00 * a12) * id;
    const float i22 = (a00 * a11 - a01 * a01) * id;

    // Cholesky (fp32)
    const float l00 = sqrtf(a00);
    const float il00 = 1.0f / l00;
    const float l10 = a01 * il00;
    const float l20 = a02 * il00;
    const float l11 = sqrtf(a11 - l10 * l10);
    const float l21 = (a12 - l20 * l10) / l11;
    const float l22 = sqrtf(a22 - l20 * l20 - l21 * l21);

    // A = 8 * L * Ginv
    const float A00 = 8.0f * (l00 * i00);
    const float A01 = 8.0f * (l00 * i01);
    const float A02 = 8.0f * (l00 * i02);
    const float A10 = 8.0f * (l10 * i00 + l11 * i01);
    const float A11 = 8.0f * (l10 * i01 + l11 * i11);
    const float A12 = 8.0f * (l10 * i02 + l11 * i12);
    const float A20 = 8.0f * (l20 * i00 + l21 * i01 + l22 * i02);
    const float A21 = 8.0f * (l20 * i01 + l21 * i11 + l22 * i12);
    const float A22 = 8.0f * (l20 * i02 + l21 * i12 + l22 * i22);

    const float bg = 1.1313708498984762f;  // sqrt(2*8*0.08)

    float* m = g_mats;
    m[ 0 * N_PIX + p] = A00; m[ 1 * N_PIX + p] = A01; m[ 2 * N_PIX + p] = A02;
    m[ 3 * N_PIX + p] = A10; m[ 4 * N_PIX + p] = A11; m[ 5 * N_PIX + p] = A12;
    m[ 6 * N_PIX + p] = A20; m[ 7 * N_PIX + p] = A21; m[ 8 * N_PIX + p] = A22;
    m[ 9 * N_PIX + p] = 8.0f * l00;
    m[10 * N_PIX + p] = 8.0f * l10;
    m[11 * N_PIX + p] = 8.0f * l11;
    m[12 * N_PIX + p] = 8.0f * l20;
    m[13 * N_PIX + p] = 8.0f * l21;
    m[14 * N_PIX + p] = 8.0f * l22;
    m[15 * N_PIX + p] = bg * l00;
    m[16 * N_PIX + p] = bg * (l10 + l11);
    m[17 * N_PIX + p] = bg * (l20 + l21 + l22);
}

// ---------------------------------------------------------------------------
// Kernel 3: streaming apply (unchanged from 64.0us baseline — at the measured
// mixed read/write DRAM ceiling, ~6.5 TB/s effective).
// ---------------------------------------------------------------------------
__global__ __launch_bounds__(256) void k_apply(const float4* __restrict__ u4,
                                               float4* __restrict__ out4) {
    const int idx = blockIdx.x * blockDim.x + threadIdx.x;  // 0..262143
    const int q   = idx & (N_Q - 1);
    const int bq  = idx >> 14;  // 0..15

    const float4* m4 = (const float4*)g_mats;
    const float4 A00 = __ldg(m4 +  0 * N_Q + q), A01 = __ldg(m4 +  1 * N_Q + q), A02 = __ldg(m4 +  2 * N_Q + q);
    const float4 A10 = __ldg(m4 +  3 * N_Q + q), A11 = __ldg(m4 +  4 * N_Q + q), A12 = __ldg(m4 +  5 * N_Q + q);
    const float4 A20 = __ldg(m4 +  6 * N_Q + q), A21 = __ldg(m4 +  7 * N_Q + q), A22 = __ldg(m4 +  8 * N_Q + q);
    const float4 L00 = __ldg(m4 +  9 * N_Q + q);
    const float4 L10 = __ldg(m4 + 10 * N_Q + q), L11 = __ldg(m4 + 11 * N_Q + q);
    const float4 L20 = __ldg(m4 + 12 * N_Q + q), L21 = __ldg(m4 + 13 * N_Q + q), L22 = __ldg(m4 + 14 * N_Q + q);
    const float4 D0  = __ldg(m4 + 15 * N_Q + q), D1 = __ldg(m4 + 16 * N_Q + q), D2 = __ldg(m4 + 17 * N_Q + q);

    const size_t diff_off = (size_t)BATCH * 6 * N_Q;  // 6291456 float4
    const float4 zero = make_float4(0.f, 0.f, 0.f, 0.f);
    const float cg = 0.64f;  // 0.64 * G * Ginv == 0.64 * I (fp32 rounding level)

#pragma unroll
    for (int i = 0; i < 4; ++i) {
        const int b = bq * 4 + i;
        const float4* ub = u4 + (size_t)b * (6 * N_Q) + q;
        const float4 x0 = __ldcs(ub);
        const float4 x1 = __ldcs(ub + N_Q);
        const float4 x2 = __ldcs(ub + 2 * N_Q);
        const float4 r0 = __ldcs(ub + 3 * N_Q);
        const float4 r1 = __ldcs(ub + 4 * N_Q);
        const float4 r2 = __ldcs(ub + 5 * N_Q);

        // drift_x = A r
        const float4 dx0 = f4fma(A02, r2, f4fma(A01, r1, f4mul(A00, r0)));
        const float4 dx1 = f4fma(A12, r2, f4fma(A11, r1, f4mul(A10, r0)));
        const float4 dx2 = f4fma(A22, r2, f4fma(A21, r1, f4mul(A20, r0)));
        // drift_r = -( (8L) x + 0.64 r )
        const float4 dr0 = f4neg(f4fma(L00, x0, f4scale(r0, cg)));
        const float4 dr1 = f4neg(f4fma(L11, x1, f4fma(L10, x0, f4scale(r1, cg))));
        const float4 dr2 = f4neg(f4fma(L22, x2, f4fma(L21, x1, f4fma(L20, x0, f4scale(r2, cg)))));

        float4* ob = out4 + (size_t)b * (6 * N_Q) + q;
        __stcs(ob + 0 * N_Q, dx0);
        __stcs(ob + 1 * N_Q, dx1);
        __stcs(ob + 2 * N_Q, dx2);
        __stcs(ob + 3 * N_Q, dr0);
        __stcs(ob + 4 * N_Q, dr1);
        __stcs(ob + 5 * N_Q, dr2);

        float4* db = ob + diff_off;
        __stcs(db + 0 * N_Q, zero);
        __stcs(db + 1 * N_Q, zero);
        __stcs(db + 2 * N_Q, zero);
        __stcs(db + 3 * N_Q, D0);
        __stcs(db + 4 * N_Q, D1);
        __stcs(db + 5 * N_Q, D2);
    }
}

// ---------------------------------------------------------------------------
extern "C" void kernel_launch(void* const* d_in, const int* in_sizes, int n_in,
                              void* d_out, int out_size) {
    const float4* u4 = (const float4*)d_in[0];   // [64, 6, 256, 256]
    const float4* s4 = (const float4*)d_in[1];   // [64, 3, 256, 256]
    const float*  t  = (const float*)d_in[2];    // [64]
    float4* out4 = (float4*)d_out;               // drift + diffusion

    k_covar<<<NBLK_COV, 128>>>(s4);
    k_prep<<<N_PIX / 256, 256>>>(t);
    k_apply<<<(N_Q * 16) / 256, 256>>>(u4, out4);
}